// round 12
// baseline (speedup 1.0000x reference)
#include <cuda_runtime.h>
#include <cstdint>

#define N_FFT   4096
#define THREADS 256
// even two-level skew: keeps quads {4g..4g+3} contiguous AND 16B-aligned so the
// fused final stage can read each group with LDS.128; conflict-free in all stages.
#define SKEW(i) ((i) + 2 * (((i) >> 4) + ((i) >> 8)))
#define BUF_ELEMS 2316                 // SKEW(2047)=2315

typedef unsigned long long u64;

// ---- packed f32x2 helpers (Blackwell): one instruction per complex add/sub ----
__device__ __forceinline__ u64 PK(float x, float y){
    u64 u; asm("mov.b64 %0, {%1, %2};" : "=l"(u) : "f"(x), "f"(y)); return u;
}
__device__ __forceinline__ float2 UP(u64 u){
    float2 a; asm("mov.b64 {%0, %1}, %2;" : "=f"(a.x), "=f"(a.y) : "l"(u)); return a;
}
__device__ __forceinline__ u64 padd(u64 a, u64 b){
    u64 r; asm("add.rn.f32x2 %0, %1, %2;" : "=l"(r) : "l"(a), "l"(b)); return r;
}
// a - b  ==  fma(b, -1, a)   (avoids relying on sub.f32x2)
__device__ __forceinline__ u64 psub(u64 a, u64 b, u64 n1){
    u64 r; asm("fma.rn.f32x2 %0, %1, %2, %3;" : "=l"(r) : "l"(b), "l"(n1), "l"(a)); return r;
}
__device__ __forceinline__ u64 pmuli(u64 u){           // *(+i): (x,y) -> (-y, x)
    float2 a = UP(u); return PK(-a.y, a.x);
}

__device__ __forceinline__ float2 cmul(float2 a, float2 b){
    return make_float2(fmaf(a.x, b.x, -a.y*b.y), fmaf(a.x, b.y, a.y*b.x));
}

// 8-point DFT core, omega8 = e^{+2*pi*i/8} (positive-sign), packed arithmetic.
__device__ __forceinline__ void dft8p(const u64 a[8], u64 b[8], u64 N1) {
    u64 t0 = padd(a[0], a[4]);
    u64 t1 = psub(a[0], a[4], N1);
    u64 t2 = padd(a[2], a[6]);
    u64 t3 = pmuli(psub(a[2], a[6], N1));
    u64 u0 = padd(a[1], a[5]);
    u64 u1 = psub(a[1], a[5], N1);
    u64 u2 = padd(a[3], a[7]);
    u64 u3 = pmuli(psub(a[3], a[7], N1));

    u64 E0 = padd(t0, t2), E2 = psub(t0, t2, N1);
    u64 E1 = padd(t1, t3), E3 = psub(t1, t3, N1);
    u64 O0 = padd(u0, u2), O2 = psub(u0, u2, N1);
    u64 O1 = padd(u1, u3), O3 = psub(u1, u3, N1);

    const float r = 0.7071067811865476f;
    float2 o1 = UP(O1);
    u64 W1 = PK(r * (o1.x - o1.y),  r * (o1.x + o1.y));   // omega8^1 * O1
    u64 W2 = pmuli(O2);                                   // omega8^2 * O2
    float2 o3 = UP(O3);
    u64 W3 = PK(-r * (o3.x + o3.y), r * (o3.x - o3.y));   // omega8^3 * O3

    b[0] = padd(E0, O0); b[4] = psub(E0, O0, N1);
    b[1] = padd(E1, W1); b[5] = psub(E1, W1, N1);
    b[2] = padd(E2, W2); b[6] = psub(E2, W2, N1);
    b[3] = padd(E3, W3); b[7] = psub(E3, W3, N1);
}

// storage quad index of the length-4 group whose DFT outputs land at
// frequencies B + 512*d (d=0..3); inverse of the 3-stage DIF digit map.
__device__ __forceinline__ int grp(int B) {
    return 2 * (((B & 7) << 5) + (((B >> 3) & 7) << 2) + ((B >> 7) & 3))
           + ((B >> 6) & 1);
}

__global__ void __launch_bounds__(THREADS, 4)
idct_fft_kernel(const float* __restrict__ x, float* __restrict__ y) {
    __shared__ __align__(16) u64 buf[BUF_ELEMS];
    __shared__ float2 lut2[32][7];     // stage-2 twiddles: w^j, w=e^{2*pi*i*p/256}
    __shared__ float2 lut3[4][7];      // stage-3 twiddles: w^j, w=e^{2*pi*i*p/32}
    const int t = threadIdx.x;
    const size_t rowoff = (size_t)blockIdx.x * N_FFT;
    const float* __restrict__ xr = x + rowoff;
    const u64 N1 = PK(-1.0f, -1.0f);

    // ---- fill twiddle LUTs (visible after the stage-1 __syncthreads) ----
    if (t < 224) {
        int p = t / 7, j = t - 7 * p + 1;
        float s, c;
        __sincosf((float)(p * j) * 2.4543692606170259e-2f, &s, &c);  // 2*pi/256
        lut2[p][j - 1] = make_float2(c, s);
    } else if (t < 252) {
        int i = t - 224, p = i / 7, j = i - 7 * p + 1;
        float s, c;
        __sincosf((float)(p * j) * 1.9634954084936207e-1f, &s, &c);  // 2*pi/32
        lut3[p][j - 1] = make_float2(c, s);
    }

    u64 a[8], b[8];

    // ---- prologue fused with stage 1 of DFT_2048 ----
    // V_k = e^{i*pi*k/8192}(x_k - i x_{4096-k});  V_0 = x_0 special.
    // Z_k = (V_k + V_{k+2048}) + i * e^{i*pi*k/2048} * (V_k - V_{k+2048}).
    float s0, c0;
    __sincosf((float)t * 3.8349519697141028e-4f, &s0, &c0);   // pi/8192
    const float2 e0 = make_float2(c0, s0);
    float2 f2 = cmul(e0, e0);
    float2 f4 = cmul(f2, f2);                                 // e^{i*pi*t/2048}
    float2 f8 = cmul(f4, f4);                                 // e^{2*pi*i*t/2048}

    // E_j = e^{i*pi*j/32}
    const float EC[8] = { 1.0f, 0.9951847266721969f, 0.9807852804032304f,
                          0.9569403357322089f, 0.9238795325112868f,
                          0.8819212643483551f, 0.8314696123025452f,
                          0.7730104533627370f };
    const float ES[8] = { 0.0f, 0.0980171403295606f, 0.1950903220161283f,
                          0.2902846772544624f, 0.3826834323650898f,
                          0.4713967368259976f, 0.5555702330196022f,
                          0.6343932841636455f };
    // G_j = e^{i*pi*j/8}
    const float GC[8] = { 1.0f,  0.9238795325112868f,  0.7071067811865476f,
                          0.3826834323650898f,  0.0f, -0.3826834323650898f,
                         -0.7071067811865476f, -0.9238795325112868f };
    const float GS[8] = { 0.0f,  0.3826834323650898f,  0.7071067811865476f,
                          0.9238795325112868f,  1.0f,  0.9238795325112868f,
                          0.7071067811865476f,  0.3826834323650898f };
    const float R2 = 0.7071067811865476f;

#pragma unroll
    for (int j = 0; j < 8; j++) {
        int   k  = t + 256 * j;                               // 0..2047
        float xa = __ldg(xr + k);
        float xb = __ldg(xr + ((N_FFT - k) & (N_FFT - 1)));
        float xc = __ldg(xr + (k + 2048));
        float xd = __ldg(xr + (2048 - k));
        // e_k = e0 * E_j = e^{i*pi*k/8192}
        float ekx = fmaf(e0.x, EC[j], -e0.y * ES[j]);
        float eky = fmaf(e0.x, ES[j],  e0.y * EC[j]);
        // V_k
        float v1x = fmaf(ekx, xa,  eky * xb);
        float v1y = fmaf(eky, xa, -ekx * xb);
        if (t == 0 && j == 0) { v1x = xa; v1y = 0.0f; }       // V_0 = x_0
        // V_{k+2048}: phase e_k * e^{i*pi/4}
        float c2x = R2 * (ekx - eky);
        float c2y = R2 * (ekx + eky);
        float v2x = fmaf(c2x, xc,  c2y * xd);
        float v2y = fmaf(c2y, xc, -c2x * xd);
        float Sx = v1x + v2x, Sy = v1y + v2y;
        float Dx = v1x - v2x, Dy = v1y - v2y;
        // e4k = e^{i*pi*k/2048} = f4 * G_j
        float e4x = fmaf(f4.x, GC[j], -f4.y * GS[j]);
        float e4y = fmaf(f4.x, GS[j],  f4.y * GC[j]);
        float edx = fmaf(e4x, Dx, -e4y * Dy);
        float edy = fmaf(e4x, Dy,  e4y * Dx);
        a[j] = PK(Sx - edy, Sy + edx);                        // Z = S + i*(e4k*D)
    }
    dft8p(a, b, N1);
    {   // stage-1 twiddles: w1 = f8, powers via log-depth chain (LUT too big here)
        float2 w1 = f8;
        float2 w2 = cmul(w1, w1);
        float2 w3 = cmul(w2, w1);
        float2 w4 = cmul(w2, w2);
        float2 w5 = cmul(w3, w2);
        float2 w6 = cmul(w3, w3);
        float2 w7 = cmul(w4, w3);
        float2 t1 = cmul(UP(b[1]), w1); b[1] = PK(t1.x, t1.y);
        float2 t2 = cmul(UP(b[2]), w2); b[2] = PK(t2.x, t2.y);
        float2 t3 = cmul(UP(b[3]), w3); b[3] = PK(t3.x, t3.y);
        float2 t4 = cmul(UP(b[4]), w4); b[4] = PK(t4.x, t4.y);
        float2 t5 = cmul(UP(b[5]), w5); b[5] = PK(t5.x, t5.y);
        float2 t6 = cmul(UP(b[6]), w6); b[6] = PK(t6.x, t6.y);
        float2 t7 = cmul(UP(b[7]), w7); b[7] = PK(t7.x, t7.y);
    }
#pragma unroll
    for (int j = 0; j < 8; j++) buf[SKEW(t + 256 * j)] = b[j];
    __syncthreads();

    // ---- stage 2 (L = 256, stride 32), twiddles from LUT ----
    {
        const int B = (t >> 5) << 8, p = t & 31;
#pragma unroll
        for (int j = 0; j < 8; j++) a[j] = buf[SKEW(B + p + 32 * j)];
        dft8p(a, b, N1);
#pragma unroll
        for (int j = 1; j < 8; j++) {
            float2 w = lut2[p][j - 1];
            float2 v = cmul(UP(b[j]), w);
            b[j] = PK(v.x, v.y);
        }
#pragma unroll
        for (int j = 0; j < 8; j++) buf[SKEW(B + p + 32 * j)] = b[j];
    }
    __syncthreads();

    // ---- stage 3 (L = 32, stride 4), twiddles from LUT ----
    {
        const int B = (t >> 2) << 5, p = t & 3;
#pragma unroll
        for (int j = 0; j < 8; j++) a[j] = buf[SKEW(B + p + 4 * j)];
        dft8p(a, b, N1);
#pragma unroll
        for (int j = 1; j < 8; j++) {
            float2 w = lut3[p][j - 1];
            float2 v = cmul(UP(b[j]), w);
            b[j] = PK(v.x, v.y);
        }
#pragma unroll
        for (int j = 0; j < 8; j++) buf[SKEW(B + p + 4 * j)] = b[j];
    }
    __syncthreads();

    // ---- fused stage 4 (radix-4, no twiddles) + epilogue ----
    // Quad grp(B) holds the length-4 group whose dft4 outputs are w_{B+512d}.
    // Mirror identity: group 511-t produces the mirrors of group t's outputs,
    // so one thread owns all 8 w-values for rows j in {t, t+512, 511-t, 1023-t}.
    float2 wA[4], wB[4];
    {
        int g = grp(t);
        ulonglong2 q0 = *(const ulonglong2*)&buf[SKEW(4 * g)];
        ulonglong2 q1 = *(const ulonglong2*)&buf[SKEW(4 * g) + 2];
        u64 s02 = padd(q0.x, q1.x), d02 = psub(q0.x, q1.x, N1);
        u64 s13 = padd(q0.y, q1.y), d13 = pmuli(psub(q0.y, q1.y, N1));
        wA[0] = UP(padd(s02, s13));        // w_t
        wA[1] = UP(padd(d02, d13));        // w_{t+512}
        wA[2] = UP(psub(s02, s13, N1));    // w_{t+1024}
        wA[3] = UP(psub(d02, d13, N1));    // w_{t+1536}
    }
    {
        int g = grp(511 - t);
        ulonglong2 q0 = *(const ulonglong2*)&buf[SKEW(4 * g)];
        ulonglong2 q1 = *(const ulonglong2*)&buf[SKEW(4 * g) + 2];
        u64 s02 = padd(q0.x, q1.x), d02 = psub(q0.x, q1.x, N1);
        u64 s13 = padd(q0.y, q1.y), d13 = pmuli(psub(q0.y, q1.y, N1));
        wB[0] = UP(padd(s02, s13));        // w_{511-t}
        wB[1] = UP(padd(d02, d13));        // w_{1023-t}
        wB[2] = UP(psub(s02, s13, N1));    // w_{1535-t}
        wB[3] = UP(psub(d02, d13, N1));    // w_{2047-t}
    }

    // y[4j..4j+3] = (Re w_j, Im w_{2047-j}, Im w_j, Re w_{2047-j})
    float4* o4 = (float4*)(y + rowoff);
    o4[t       ] = make_float4(wA[0].x, wB[3].y, wA[0].y, wB[3].x);  // j = t
    o4[t + 512 ] = make_float4(wA[1].x, wB[2].y, wA[1].y, wB[2].x);  // j = t+512
    o4[511 - t ] = make_float4(wB[0].x, wA[3].y, wB[0].y, wA[3].x);  // j = 511-t
    o4[1023 - t] = make_float4(wB[1].x, wA[2].y, wB[1].y, wA[2].x);  // j = 1023-t
}

extern "C" void kernel_launch(void* const* d_in, const int* in_sizes, int n_in,
                              void* d_out, int out_size) {
    (void)n_in; (void)out_size;
    const float* x = (const float*)d_in[0];
    float*       y = (float*)d_out;
    int rows = in_sizes[0] / N_FFT;      // 4096 for this problem
    idct_fft_kernel<<<rows, THREADS>>>(x, y);
}

// round 13
// speedup vs baseline: 1.0488x; 1.0488x over previous
#include <cuda_runtime.h>
#include <cstdint>

#define N_FFT   4096
#define THREADS 256
// even two-level skew: keeps quads {4g..4g+3} contiguous AND 16B-aligned so the
// fused final stage can read each group with LDS.128; conflict-free in all stages.
#define SKEW(i) ((i) + 2 * (((i) >> 4) + ((i) >> 8)))
#define BUF_ELEMS 2316                 // SKEW(2047)=2315

__device__ __forceinline__ float2 cadd(float2 a, float2 b){ return make_float2(a.x+b.x, a.y+b.y); }
__device__ __forceinline__ float2 csub(float2 a, float2 b){ return make_float2(a.x-b.x, a.y-b.y); }
__device__ __forceinline__ float2 cmul(float2 a, float2 b){
    return make_float2(fmaf(a.x, b.x, -a.y*b.y), fmaf(a.x, b.y, a.y*b.x));
}
__device__ __forceinline__ float2 cmuli(float2 a){ return make_float2(-a.y, a.x); }   // *(+i)

// 8-point DFT core, omega8 = e^{+2*pi*i/8}  (positive-sign DFT)
__device__ __forceinline__ void dft8(const float2 a[8], float2 b[8]) {
    float2 t0 = cadd(a[0], a[4]);
    float2 t1 = csub(a[0], a[4]);
    float2 t2 = cadd(a[2], a[6]);
    float2 t3 = cmuli(csub(a[2], a[6]));
    float2 u0 = cadd(a[1], a[5]);
    float2 u1 = csub(a[1], a[5]);
    float2 u2 = cadd(a[3], a[7]);
    float2 u3 = cmuli(csub(a[3], a[7]));

    float2 E0 = cadd(t0, t2), E2 = csub(t0, t2);
    float2 E1 = cadd(t1, t3), E3 = csub(t1, t3);
    float2 O0 = cadd(u0, u2), O2 = csub(u0, u2);
    float2 O1 = cadd(u1, u3), O3 = csub(u1, u3);

    const float r = 0.7071067811865476f;
    float2 W1 = make_float2(r * (O1.x - O1.y),  r * (O1.x + O1.y));   // omega8^1 * O1
    float2 W2 = cmuli(O2);                                            // omega8^2 * O2
    float2 W3 = make_float2(-r * (O3.x + O3.y), r * (O3.x - O3.y));   // omega8^3 * O3

    b[0] = cadd(E0, O0); b[4] = csub(E0, O0);
    b[1] = cadd(E1, W1); b[5] = csub(E1, W1);
    b[2] = cadd(E2, W2); b[6] = csub(E2, W2);
    b[3] = cadd(E3, W3); b[7] = csub(E3, W3);
}

// Apply twiddles b[j] *= w1^j using log-depth power generation (stage 1 only).
__device__ __forceinline__ void twiddle8w(float2 b[8], float2 w1) {
    float2 w2 = cmul(w1, w1);
    float2 w3 = cmul(w2, w1);
    float2 w4 = cmul(w2, w2);
    float2 w5 = cmul(w3, w2);
    float2 w6 = cmul(w3, w3);
    float2 w7 = cmul(w4, w3);
    b[1] = cmul(b[1], w1);
    b[2] = cmul(b[2], w2);
    b[3] = cmul(b[3], w3);
    b[4] = cmul(b[4], w4);
    b[5] = cmul(b[5], w5);
    b[6] = cmul(b[6], w6);
    b[7] = cmul(b[7], w7);
}

// storage quad index of the length-4 group whose DFT outputs land at
// frequencies B + 512*d (d=0..3); inverse of the 3-stage DIF digit map.
__device__ __forceinline__ int grp(int B) {
    return 2 * (((B & 7) << 5) + (((B >> 3) & 7) << 2) + ((B >> 7) & 3))
           + ((B >> 6) & 1);
}

__global__ void __launch_bounds__(THREADS, 4)
idct_fft_kernel(const float* __restrict__ x, float* __restrict__ y) {
    __shared__ __align__(16) float2 buf[BUF_ELEMS];
    // transposed twiddle LUTs: warp reads lut[j-1][p] with p lane-consecutive
    // -> stride-1, conflict-free.
    __shared__ float2 lut2[7][32];     // stage-2: e^{2*pi*i*p*(j)/256}, j=1..7
    __shared__ float2 lut3[7][4];      // stage-3: e^{2*pi*i*p*(j)/32},  j=1..7
    const int t = threadIdx.x;
    const size_t rowoff = (size_t)blockIdx.x * N_FFT;
    const float* __restrict__ xr = x + rowoff;

    // ---- fill twiddle LUTs (ready after the stage-1 __syncthreads) ----
    if (t < 224) {
        int j = t >> 5, p = t & 31;            // j = 0..6 meaning power j+1
        float s, c;
        __sincosf((float)(p * (j + 1)) * 2.4543692606170259e-2f, &s, &c); // 2*pi/256
        lut2[j][p] = make_float2(c, s);
    } else if (t < 252) {
        int i = t - 224, j = i >> 2, p = i & 3;
        float s, c;
        __sincosf((float)(p * (j + 1)) * 1.9634954084936207e-1f, &s, &c); // 2*pi/32
        lut3[j][p] = make_float2(c, s);
    }

    float2 a[8], b[8];

    // ---- prologue fused with stage 1 of DFT_2048 ----
    // V_k = e^{i*pi*k/8192}(x_k - i x_{4096-k});  V_0 = x_0 special.
    // Z_k = (V_k + V_{k+2048}) + i * e^{i*pi*k/2048} * (V_k - V_{k+2048}).
    float s0, c0;
    __sincosf((float)t * 3.8349519697141028e-4f, &s0, &c0);   // pi/8192
    const float2 e0 = make_float2(c0, s0);
    float2 f2 = cmul(e0, e0);
    float2 f4 = cmul(f2, f2);                                 // e^{i*pi*t/2048}
    float2 f8 = cmul(f4, f4);                                 // e^{2*pi*i*t/2048}

    // E_j = e^{i*pi*j/32}
    const float EC[8] = { 1.0f, 0.9951847266721969f, 0.9807852804032304f,
                          0.9569403357322089f, 0.9238795325112868f,
                          0.8819212643483551f, 0.8314696123025452f,
                          0.7730104533627370f };
    const float ES[8] = { 0.0f, 0.0980171403295606f, 0.1950903220161283f,
                          0.2902846772544624f, 0.3826834323650898f,
                          0.4713967368259976f, 0.5555702330196022f,
                          0.6343932841636455f };
    // G_j = e^{i*pi*j/8}
    const float GC[8] = { 1.0f,  0.9238795325112868f,  0.7071067811865476f,
                          0.3826834323650898f,  0.0f, -0.3826834323650898f,
                         -0.7071067811865476f, -0.9238795325112868f };
    const float GS[8] = { 0.0f,  0.3826834323650898f,  0.7071067811865476f,
                          0.9238795325112868f,  1.0f,  0.9238795325112868f,
                          0.7071067811865476f,  0.3826834323650898f };
    const float R2 = 0.7071067811865476f;

#pragma unroll
    for (int j = 0; j < 8; j++) {
        int   k  = t + 256 * j;                               // 0..2047
        float xa = __ldg(xr + k);
        float xb = __ldg(xr + ((N_FFT - k) & (N_FFT - 1)));
        float xc = __ldg(xr + (k + 2048));
        float xd = __ldg(xr + (2048 - k));
        // e_k = e0 * E_j = e^{i*pi*k/8192}
        float ekx = fmaf(e0.x, EC[j], -e0.y * ES[j]);
        float eky = fmaf(e0.x, ES[j],  e0.y * EC[j]);
        // V_k
        float v1x = fmaf(ekx, xa,  eky * xb);
        float v1y = fmaf(eky, xa, -ekx * xb);
        if (t == 0 && j == 0) { v1x = xa; v1y = 0.0f; }       // V_0 = x_0
        // V_{k+2048}: phase e_k * e^{i*pi/4}
        float c2x = R2 * (ekx - eky);
        float c2y = R2 * (ekx + eky);
        float v2x = fmaf(c2x, xc,  c2y * xd);
        float v2y = fmaf(c2y, xc, -c2x * xd);
        float Sx = v1x + v2x, Sy = v1y + v2y;
        float Dx = v1x - v2x, Dy = v1y - v2y;
        // e4k = e^{i*pi*k/2048} = f4 * G_j
        float e4x = fmaf(f4.x, GC[j], -f4.y * GS[j]);
        float e4y = fmaf(f4.x, GS[j],  f4.y * GC[j]);
        float edx = fmaf(e4x, Dx, -e4y * Dy);
        float edy = fmaf(e4x, Dy,  e4y * Dx);
        a[j] = make_float2(Sx - edy, Sy + edx);               // Z = S + i*(e4k*D)
    }
    dft8(a, b);
    twiddle8w(b, f8);
#pragma unroll
    for (int j = 0; j < 8; j++) buf[SKEW(t + 256 * j)] = b[j];
    __syncthreads();

    // ---- stage 2 (L = 256, stride 32), twiddles from LUT ----
    {
        const int B = (t >> 5) << 8, p = t & 31;
#pragma unroll
        for (int j = 0; j < 8; j++) a[j] = buf[SKEW(B + p + 32 * j)];
        dft8(a, b);
#pragma unroll
        for (int j = 1; j < 8; j++) b[j] = cmul(b[j], lut2[j - 1][p]);
#pragma unroll
        for (int j = 0; j < 8; j++) buf[SKEW(B + p + 32 * j)] = b[j];
    }
    __syncthreads();

    // ---- stage 3 (L = 32, stride 4), twiddles from LUT ----
    {
        const int B = (t >> 2) << 5, p = t & 3;
#pragma unroll
        for (int j = 0; j < 8; j++) a[j] = buf[SKEW(B + p + 4 * j)];
        dft8(a, b);
#pragma unroll
        for (int j = 1; j < 8; j++) b[j] = cmul(b[j], lut3[j - 1][p]);
#pragma unroll
        for (int j = 0; j < 8; j++) buf[SKEW(B + p + 4 * j)] = b[j];
    }
    __syncthreads();

    // ---- fused stage 4 (radix-4, no twiddles) + epilogue ----
    // Quad grp(B) holds the length-4 group whose dft4 outputs are w_{B+512d}.
    // Mirror identity: group 511-t produces exactly the mirrors of group t's
    // outputs, so ONE thread computing BOTH full dft4s owns all 8 w-values for
    // output rows j in {t, t+512, 511-t, 1023-t}.
    float2 wA[4], wB[4];
    {
        int g = grp(t);
        float4 q0 = *(const float4*)&buf[SKEW(4 * g)];
        float4 q1 = *(const float4*)&buf[SKEW(4 * g) + 2];
        float2 z0 = make_float2(q0.x, q0.y), z1 = make_float2(q0.z, q0.w);
        float2 z2 = make_float2(q1.x, q1.y), z3 = make_float2(q1.z, q1.w);
        float2 s02 = cadd(z0, z2), s13 = cadd(z1, z3);
        float2 d02 = csub(z0, z2), d13 = cmuli(csub(z1, z3));
        wA[0] = cadd(s02, s13);   // w_t
        wA[1] = cadd(d02, d13);   // w_{t+512}
        wA[2] = csub(s02, s13);   // w_{t+1024}
        wA[3] = csub(d02, d13);   // w_{t+1536}
    }
    {
        int g = grp(511 - t);
        float4 q0 = *(const float4*)&buf[SKEW(4 * g)];
        float4 q1 = *(const float4*)&buf[SKEW(4 * g) + 2];
        float2 z0 = make_float2(q0.x, q0.y), z1 = make_float2(q0.z, q0.w);
        float2 z2 = make_float2(q1.x, q1.y), z3 = make_float2(q1.z, q1.w);
        float2 s02 = cadd(z0, z2), s13 = cadd(z1, z3);
        float2 d02 = csub(z0, z2), d13 = cmuli(csub(z1, z3));
        wB[0] = cadd(s02, s13);   // w_{511-t}
        wB[1] = cadd(d02, d13);   // w_{1023-t}
        wB[2] = csub(s02, s13);   // w_{1535-t}
        wB[3] = csub(d02, d13);   // w_{2047-t}
    }

    // y[4j..4j+3] = (Re w_j, Im w_{2047-j}, Im w_j, Re w_{2047-j})
    float4* o4 = (float4*)(y + rowoff);
    o4[t       ] = make_float4(wA[0].x, wB[3].y, wA[0].y, wB[3].x);  // j = t
    o4[t + 512 ] = make_float4(wA[1].x, wB[2].y, wA[1].y, wB[2].x);  // j = t+512
    o4[511 - t ] = make_float4(wB[0].x, wA[3].y, wB[0].y, wA[3].x);  // j = 511-t
    o4[1023 - t] = make_float4(wB[1].x, wA[2].y, wB[1].y, wA[2].x);  // j = 1023-t
}

extern "C" void kernel_launch(void* const* d_in, const int* in_sizes, int n_in,
                              void* d_out, int out_size) {
    (void)n_in; (void)out_size;
    const float* x = (const float*)d_in[0];
    float*       y = (float*)d_out;
    int rows = in_sizes[0] / N_FFT;      // 4096 for this problem
    idct_fft_kernel<<<rows, THREADS>>>(x, y);
}